// round 14
// baseline (speedup 1.0000x reference)
#include <cuda_runtime.h>
#include <cuda_fp16.h>
#include <cstdint>

#define N_NODES 50000
#define N_EDGES 400000
#define IN_C 128
#define HID 256

typedef __half h16;

// ---------------- scratch (device globals) ---------------------------------
__device__ __align__(16) h16  g_xhi[(size_t)N_NODES * 128];
__device__ __align__(16) h16  g_xlo[(size_t)N_NODES * 128];
__device__ __align__(16) h16  g_hAhi[(size_t)N_NODES * 256];
__device__ __align__(16) h16  g_hAlo[(size_t)N_NODES * 256];
__device__ __align__(16) h16  g_hBhi[(size_t)N_NODES * 256];
__device__ __align__(16) h16  g_hBlo[(size_t)N_NODES * 256];
__device__ __align__(16) h16  g_agghi[(size_t)N_NODES * 256];
__device__ __align__(16) h16  g_agglo[(size_t)N_NODES * 256];
__device__ __align__(16) float g_aggsum[(size_t)N_NODES * 256];  // fp32 accumulation
__device__ __align__(16) h16   g_psrc[(size_t)N_NODES * 256];    // src-proj fp16
__device__ __align__(16) float g_pdst[(size_t)N_NODES * 256];    // dst-proj fp32
__device__ __align__(16) h16  g_eahi[(size_t)N_EDGES * 32];
__device__ __align__(16) h16  g_ealo[(size_t)N_EDGES * 32];
__device__ __align__(16) uint32_t g_w[389120];
__device__ int g_srcperm[N_EDGES];
__device__ int g_nodeof[N_EDGES];
__device__ int g_deg[N_NODES], g_rowptr[N_NODES + 1], g_cursor[N_NODES];

// piece tables (weight slicing)
__constant__ int c_psel[16]  = {0,0,0,1,1,2,2,2,3,3,3,4,4,5,5,6};
__constant__ int c_prow0[16] = {0,128,256,0,128,0,256,512,0,256,512,0,256,0,256,0};
__constant__ int c_pkw[16]   = {64,64,16,64,128,128,128,16,128,128,16,128,128,128,128,128};
__constant__ int c_poff[17]  = {0,16384,32768,36864,53248,86016,118784,151552,155648,
                                188416,221184,225280,258048,290816,323584,356352,389120};
#define PO0 0
#define PO1 16384
#define PO2 32768
#define PO3 36864
#define PO4 53248
#define PO5 86016
#define PO6 118784
#define PO7 151552
#define PO8 155648
#define PO9 188416
#define PO10 221184
#define PO11 225280
#define PO12 258048
#define PO13 290816
#define PO14 323584
#define PO15 356352

// ---------------- helpers ---------------------------------------------------
__device__ __forceinline__ void pack2h(float a, float b, uint32_t& hi, uint32_t& lo) {
    __half2 h = __floats2half2_rn(a, b);
    __half2 l = __floats2half2_rn(a - __low2float(h), b - __high2float(h));
    hi = *reinterpret_cast<uint32_t*>(&h);
    lo = *reinterpret_cast<uint32_t*>(&l);
}
__device__ __forceinline__ void mma_f16(float* c, const uint32_t* a, const uint32_t* b) {
    asm volatile(
        "mma.sync.aligned.m16n8k16.row.col.f32.f16.f16.f32 "
        "{%0,%1,%2,%3}, {%4,%5,%6,%7}, {%8,%9}, {%0,%1,%2,%3};"
        : "+f"(c[0]), "+f"(c[1]), "+f"(c[2]), "+f"(c[3])
        : "r"(a[0]), "r"(a[1]), "r"(a[2]), "r"(a[3]), "r"(b[0]), "r"(b[1]));
}
__device__ __forceinline__ void ldsm4(uint32_t addr, uint32_t* r) {
    asm volatile("ldmatrix.sync.aligned.m8n8.x4.shared.b16 {%0,%1,%2,%3}, [%4];"
                 : "=r"(r[0]), "=r"(r[1]), "=r"(r[2]), "=r"(r[3]) : "r"(addr));
}
__device__ __forceinline__ void cp_async16(uint32_t daddr, const void* gptr, int src_size) {
    asm volatile("cp.async.cg.shared.global [%0], [%1], 16, %2;"
                 :: "r"(daddr), "l"(gptr), "r"(src_size));
}
#define CP_COMMIT() asm volatile("cp.async.commit_group;" ::: "memory")
#define CP_WAIT1()  asm volatile("cp.async.wait_group 1;" ::: "memory")
#define CP_WAIT0()  asm volatile("cp.async.wait_group 0;" ::: "memory")

// ---------------- fused prep: weights + x split + zeroing + out init --------
#define WPREP_BLKS 1520
#define APREP_BLKS 1024
#define ZERO_BLKS  64
#define AGGZ_BLKS  512
__global__ void prep_all(const float* __restrict__ p0, const float* __restrict__ p1,
                         const float* __restrict__ p2, const float* __restrict__ p3,
                         const float* __restrict__ p4, const float* __restrict__ p5,
                         const float* __restrict__ p6, uint32_t* __restrict__ w,
                         const float* __restrict__ X, h16* __restrict__ xhi, h16* __restrict__ xlo,
                         int* __restrict__ deg, float* __restrict__ outv,
                         const float* __restrict__ h2b, float* __restrict__ aggsum) {
    int b = blockIdx.x;
    if (b < WPREP_BLKS) {
        const float* P[7] = {p0, p1, p2, p3, p4, p5, p6};
        const int total = 389120;
        for (int idx = b * blockDim.x + threadIdx.x; idx < total; idx += WPREP_BLKS * blockDim.x) {
            int pc = 0;
            while (idx >= c_poff[pc + 1]) pc++;
            int local = idx - c_poff[pc];
            int Kw = c_pkw[pc];
            int n = local / Kw;
            int kp = local - n * Kw;
            const float* W = P[c_psel[pc]];
            int r = c_prow0[pc] + 2 * kp;
            __half2 h = __floats2half2_rn(W[(size_t)r * 256 + n], W[(size_t)(r + 1) * 256 + n]);
            w[idx] = *reinterpret_cast<uint32_t*>(&h);
        }
    } else if (b < WPREP_BLKS + APREP_BLKS) {
        int bb = b - WPREP_BLKS;
        size_t total = (size_t)N_NODES * 128;
        for (size_t i = (size_t)bb * blockDim.x + threadIdx.x; i < total; i += (size_t)APREP_BLKS * blockDim.x) {
            float v = X[i];
            h16 h = __float2half_rn(v);
            xhi[i] = h;
            xlo[i] = __float2half_rn(v - __half2float(h));
        }
    } else if (b < WPREP_BLKS + APREP_BLKS + ZERO_BLKS) {
        int bb = b - WPREP_BLKS - APREP_BLKS;
        float ob = h2b[0];
        for (int i = bb * blockDim.x + threadIdx.x; i < N_NODES; i += ZERO_BLKS * blockDim.x) {
            deg[i] = 0;
            outv[i] = ob;
        }
    } else {
        int bb = b - WPREP_BLKS - APREP_BLKS - ZERO_BLKS;
        size_t total = (size_t)N_NODES * 64;   // float4 groups
        float4 z = make_float4(0.f, 0.f, 0.f, 0.f);
        for (size_t i = (size_t)bb * blockDim.x + threadIdx.x; i < total; i += (size_t)AGGZ_BLKS * blockDim.x)
            *((float4*)aggsum + i) = z;
    }
}

// ---------------- CSR build ------------------------------------------------
__global__ void count_deg_kernel(const int* __restrict__ dst, int* deg, int e) {
    for (int i = blockIdx.x * blockDim.x + threadIdx.x; i < e; i += gridDim.x * blockDim.x)
        atomicAdd(&deg[dst[i]], 1);
}
__global__ void scan_kernel(const int* __restrict__ deg, int* rowptr, int* cursor, int n) {
    __shared__ int wsum[32];
    __shared__ int carry;
    int tid = threadIdx.x, lane = tid & 31, wid = tid >> 5;
    if (tid == 0) { carry = 0; rowptr[0] = 0; }
    __syncthreads();
    for (int base = 0; base < n; base += 1024) {
        int i = base + tid;
        int v = (i < n) ? deg[i] : 0;
        int cr = carry;
        int x = v;
        #pragma unroll
        for (int off = 1; off < 32; off <<= 1) {
            int t = __shfl_up_sync(0xFFFFFFFFu, x, off);
            if (lane >= off) x += t;
        }
        if (lane == 31) wsum[wid] = x;
        __syncthreads();
        if (wid == 0) {
            int s = wsum[lane];
            #pragma unroll
            for (int off = 1; off < 32; off <<= 1) {
                int t = __shfl_up_sync(0xFFFFFFFFu, s, off);
                if (lane >= off) s += t;
            }
            wsum[lane] = s;
        }
        __syncthreads();
        int warp_off = (wid > 0) ? wsum[wid - 1] : 0;
        int inc = x + warp_off + cr;
        if (i < n) { rowptr[i + 1] = inc; cursor[i] = inc - v; }
        __syncthreads();
        if (tid == 1023) carry = inc;
        __syncthreads();
    }
}
// scatter + edge-attr permute/convert fused; also records node id per CSR slot
__global__ void scatter_fused(const int* __restrict__ src, const int* __restrict__ dst,
                              const float* __restrict__ ea,
                              int* cursor, int* __restrict__ src_perm, int* __restrict__ node_of,
                              h16* __restrict__ eahi, h16* __restrict__ ealo, int e) {
    for (int i = blockIdx.x * blockDim.x + threadIdx.x; i < e; i += gridDim.x * blockDim.x) {
        int d = dst[i];
        int p = atomicAdd(&cursor[d], 1);
        src_perm[p] = src[i];
        node_of[p] = d;
        const float* row = ea + (size_t)i * 32;
        #pragma unroll
        for (int q = 0; q < 4; ++q) {
            float4 v0 = *(const float4*)(row + q * 8);
            float4 v1 = *(const float4*)(row + q * 8 + 4);
            uint32_t h0, l0, h1, l1, h2, l2, h3, l3;
            pack2h(v0.x, v0.y, h0, l0);
            pack2h(v0.z, v0.w, h1, l1);
            pack2h(v1.x, v1.y, h2, l2);
            pack2h(v1.z, v1.w, h3, l3);
            *(uint4*)(eahi + (size_t)p * 32 + q * 8) = make_uint4(h0, h1, h2, h3);
            *(uint4*)(ealo + (size_t)p * 32 + q * 8) = make_uint4(l0, l1, l2, l3);
        }
    }
}

// ---------------- 2-term fp16 GEMM body (job-parameterized) ------------------
#define A_STG 2304    // 64*36 u32 per stage
#define B_STG 2560    // 128*20 u32 per stage
#define SMEM_BYTES (3 * (A_STG + B_STG) * 4)   // 58368
#define MAXL 96       // max local nodes per edge tile (48KB smem accum)

struct GJob {
    const h16 *A1hi, *A1lo;
    const uint32_t *B1a, *B1b;
    const h16 *A2hi, *A2lo;
    const uint32_t *B2;
    const float* bias;
    const float* w2;            // mode 4: head output weights
    const int* sperm;           // mode 5
    const int* nodeof;          // mode 5
    const h16* psrcp;           // mode 5
    const float* pdstp;         // mode 5
    void *C0, *C1;
    int K1, K2, relu, mode, M, gx;
};

__device__ __forceinline__ void gemm_body(const GJob& j, int bxl) {
    extern __shared__ uint32_t dyn[];
    uint32_t sA_saddr = (uint32_t)__cvta_generic_to_shared(dyn);
    uint32_t sB_saddr = (uint32_t)__cvta_generic_to_shared(dyn + 3 * A_STG);

    int tid = threadIdx.x, wid = tid >> 5, lane = tid & 31;
    int xb = bxl % j.gx;
    int yy = bxl / j.gx;
    int bm = xb * 64;
    int bn = (yy & 1) * 128;
    int ysel = yy >> 1;
    int wm = (wid >> 2) * 32;
    int wn = (wid & 3) * 32;
    int gq = lane >> 2, tq = lane & 3;

    const uint32_t* Ah[2] = { (const uint32_t*)j.A1hi, (const uint32_t*)j.A2hi };
    const uint32_t* Al[2] = { (const uint32_t*)j.A1lo, (const uint32_t*)j.A2lo };
    const uint32_t* Bp[2] = { ysel ? j.B1b : j.B1a, j.B2 };
    int K1 = j.K1, K2 = j.K2;
    int Kw0 = K1 >> 1, Kw1 = K2 >> 1;
    int nch0 = K1 >> 5;
    int nch = nch0 + ((j.A2hi != nullptr) ? (K2 >> 5) : 0);
    int M = j.M;
    int mode = j.mode;

    float acc[2][4][4];
    #pragma unroll
    for (int mi = 0; mi < 2; mi++)
        #pragma unroll
        for (int ni = 0; ni < 4; ni++)
            #pragma unroll
            for (int q = 0; q < 4; q++) acc[mi][ni][q] = 0.f;

    int aLaneRow = ((lane >> 3) & 1) * 8 + (lane & 7);
    int aColSel  = (lane >> 4) * 4;
    uint32_t aOff = (uint32_t)(((wm + aLaneRow) * 36 + aColSel) * 4);
    int bNi      = lane >> 4;
    int bColSel  = ((lane >> 3) & 1) * 4;
    int bLaneRow = lane & 7;
    uint32_t bOff = (uint32_t)(((wn + bNi * 8 + bLaneRow) * 20 + bColSel) * 4);

    auto issue = [&](int c, int buf) {
        int seg = (c >= nch0) ? 1 : 0;
        int kw0 = (seg ? (c - nch0) : c) << 4;
        int Kw = seg ? Kw1 : Kw0;
        const uint32_t* Ahp = Ah[seg];
        const uint32_t* Alp = Al[seg];
        const uint32_t* Bpp = Bp[seg];
        uint32_t sa = sA_saddr + buf * (A_STG * 4);
        uint32_t sb = sB_saddr + buf * (B_STG * 4);
        #pragma unroll
        for (int it = 0; it < 2; ++it) {
            int s = tid + it * 256;
            int row = s >> 3, part = s & 7;
            uint32_t so = (uint32_t)((row * 36 + ((part < 4) ? (part * 4) : (16 + (part - 4) * 4))) * 4);
            int grow = bm + row;
            int ok = (grow < M);
            int r = ok ? grow : 0;
            const uint32_t* gpa = ((part < 4) ? Ahp : Alp) + (size_t)r * Kw + kw0 + (part & 3) * 4;
            cp_async16(sa + so, gpa, ok ? 16 : 0);
        }
        #pragma unroll
        for (int it = 0; it < 2; ++it) {
            int s = tid + it * 256;
            int row = s >> 2, part = s & 3;
            uint32_t so = (uint32_t)((row * 20 + part * 4) * 4);
            const uint32_t* gpb = Bpp + (size_t)(bn + row) * Kw + kw0 + part * 4;
            cp_async16(sb + so, gpb, 16);
        }
        CP_COMMIT();
    };

    issue(0, 0);
    if (nch > 1) issue(1, 1);

    #pragma unroll 1
    for (int c = 0; c < nch; ++c) {
        int buf = c - (c / 3) * 3;
        if (c + 1 < nch) { CP_WAIT1(); } else { CP_WAIT0(); }
        __syncthreads();

        uint32_t bufA = sA_saddr + buf * (A_STG * 4) + aOff;
        uint32_t bufB = sB_saddr + buf * (B_STG * 4) + bOff;
        #pragma unroll
        for (int ks = 0; ks < 2; ++ks) {
            int kb4 = ks * 32;
            uint32_t bh[4][2], t[4];
            #pragma unroll
            for (int p = 0; p < 2; ++p) {
                ldsm4(bufB + p * 1280 + kb4, t);
                bh[2 * p][0] = t[0]; bh[2 * p][1] = t[1];
                bh[2 * p + 1][0] = t[2]; bh[2 * p + 1][1] = t[3];
            }
            #pragma unroll
            for (int mi = 0; mi < 2; mi++) {
                uint32_t ah[4], al[4];
                ldsm4(bufA + mi * 2304 + kb4, ah);
                ldsm4(bufA + mi * 2304 + kb4 + 64, al);
                #pragma unroll
                for (int ni = 0; ni < 4; ni++) mma_f16(acc[mi][ni], ah, bh[ni]);
                #pragma unroll
                for (int ni = 0; ni < 4; ni++) mma_f16(acc[mi][ni], al, bh[ni]);
            }
        }
        if (c + 2 < nch) {
            int nb = (c + 2) - ((c + 2) / 3) * 3;
            issue(c + 2, nb);
        }
    }

    if (mode == 5) {
        // ---- fused edge aggregation: accumulate relu(acc+bias+psrc+pdst) ----
        float* sagg = (float*)dyn;          // reuse pipeline smem: MAXL x 128 fp32
        float* aggsum = (float*)j.C0;
        __syncthreads();                     // all warps done with stage smem
        for (int i = tid; i < MAXL * 128; i += 256) sagg[i] = 0.f;
        __syncthreads();
        int node0 = __ldg(j.nodeof + bm);
        #pragma unroll
        for (int mi = 0; mi < 2; mi++) {
            #pragma unroll
            for (int rr = 0; rr < 2; rr++) {
                int r = bm + wm + mi * 16 + gq + rr * 8;
                int sp = __ldg(j.sperm + r);
                int nd = __ldg(j.nodeof + r);
                int local = nd - node0;
                #pragma unroll
                for (int ni = 0; ni < 4; ni++) {
                    int gcol = bn + wn + ni * 8 + tq * 2;
                    float b0 = __ldg(j.bias + gcol), b1 = __ldg(j.bias + gcol + 1);
                    float2 pv = __half22float2(*(const __half2*)(j.psrcp + (size_t)sp * 256 + gcol));
                    float2 dv = *(const float2*)(j.pdstp + (size_t)nd * 256 + gcol);
                    float v0 = fmaxf(acc[mi][ni][rr * 2 + 0] + b0 + pv.x + dv.x, 0.f);
                    float v1 = fmaxf(acc[mi][ni][rr * 2 + 1] + b1 + pv.y + dv.y, 0.f);
                    if (local < MAXL) {
                        int ch = gcol - bn;
                        atomicAdd(&sagg[local * 128 + ch], v0);
                        atomicAdd(&sagg[local * 128 + ch + 1], v1);
                    } else {   // extremely rare: long run of empty nodes
                        atomicAdd(&aggsum[(size_t)nd * 256 + gcol], v0);
                        atomicAdd(&aggsum[(size_t)nd * 256 + gcol + 1], v1);
                    }
                }
            }
        }
        __syncthreads();
        int span = __ldg(j.nodeof + bm + 63) - node0;
        if (span >= MAXL) span = MAXL - 1;
        for (int i = tid; i < (span + 1) * 128; i += 256) {
            float s = sagg[i];
            if (s != 0.f) {
                int l = i >> 7, ch = i & 127;
                atomicAdd(&aggsum[(size_t)(node0 + l) * 256 + bn + ch], s);
            }
        }
        return;
    }

    // ---- standard epilogue ----
    float dot0[2] = {0.f, 0.f}, dot1[2] = {0.f, 0.f};
    #pragma unroll
    for (int mi = 0; mi < 2; mi++) {
        int r = bm + wm + mi * 16 + gq;
        #pragma unroll
        for (int ni = 0; ni < 4; ni++) {
            int gcol = bn + wn + ni * 8 + tq * 2;
            float b0 = 0.f, b1 = 0.f;
            if (j.bias) { b0 = __ldg(j.bias + gcol); b1 = __ldg(j.bias + gcol + 1); }
            float v0 = acc[mi][ni][0] + b0, v1 = acc[mi][ni][1] + b1;
            float v2 = acc[mi][ni][2] + b0, v3 = acc[mi][ni][3] + b1;
            if (j.relu) {
                v0 = fmaxf(v0, 0.f); v1 = fmaxf(v1, 0.f);
                v2 = fmaxf(v2, 0.f); v3 = fmaxf(v3, 0.f);
            }
            if (mode == 4) {
                float w0v = __ldg(j.w2 + gcol), w1v = __ldg(j.w2 + gcol + 1);
                dot0[mi] += v0 * w0v + v1 * w1v;
                dot1[mi] += v2 * w0v + v3 * w1v;
                continue;
            }
            size_t o0 = (size_t)r * 256 + gcol;
            size_t o1 = (size_t)(r + 8) * 256 + gcol;
            bool w0 = (r < M), w1 = (r + 8 < M);
            if (mode == 0 || (mode == 3 && ysel == 1)) {
                float* C = (mode == 0) ? (float*)j.C0 : (float*)j.C1;
                if (w0) *(float2*)(C + o0) = make_float2(v0, v1);
                if (w1) *(float2*)(C + o1) = make_float2(v2, v3);
            } else if (mode == 1 || mode == 3) {
                h16* C = (h16*)j.C0;
                if (w0) *(__half2*)(C + o0) = __floats2half2_rn(v0, v1);
                if (w1) *(__half2*)(C + o1) = __floats2half2_rn(v2, v3);
            } else {   // mode 2: fp16 hi/lo
                h16* Ch = (h16*)j.C0;
                h16* Cl = (h16*)j.C1;
                if (w0) {
                    uint32_t hh, ll;
                    pack2h(v0, v1, hh, ll);
                    *(uint32_t*)(Ch + o0) = hh;
                    *(uint32_t*)(Cl + o0) = ll;
                }
                if (w1) {
                    uint32_t hh, ll;
                    pack2h(v2, v3, hh, ll);
                    *(uint32_t*)(Ch + o1) = hh;
                    *(uint32_t*)(Cl + o1) = ll;
                }
            }
        }
    }
    if (mode == 4) {
        float* outv = (float*)j.C0;
        #pragma unroll
        for (int mi = 0; mi < 2; mi++) {
            float d0 = dot0[mi], d1 = dot1[mi];
            d0 += __shfl_xor_sync(0xFFFFFFFFu, d0, 1);
            d0 += __shfl_xor_sync(0xFFFFFFFFu, d0, 2);
            d1 += __shfl_xor_sync(0xFFFFFFFFu, d1, 1);
            d1 += __shfl_xor_sync(0xFFFFFFFFu, d1, 2);
            int r = bm + wm + mi * 16 + gq;
            if (tq == 0) {
                if (r < M) atomicAdd(outv + r, d0);
                if (r + 8 < M) atomicAdd(outv + r + 8, d1);
            }
        }
    }
}

__global__ __launch_bounds__(256, 3) void gemm_one(GJob j) {
    gemm_body(j, blockIdx.x);
}

// ---------------- normalize: agghi/lo = aggsum/deg; aggsum := 0 -------------
__global__ void normalize_kernel(float* __restrict__ aggsum, const int* __restrict__ deg,
                                 h16* __restrict__ agghi, h16* __restrict__ agglo) {
    int total = N_NODES * 128;   // half2 pairs
    for (int i = blockIdx.x * blockDim.x + threadIdx.x; i < total; i += gridDim.x * blockDim.x) {
        int node = i >> 7;
        float2 s = *(float2*)(aggsum + (size_t)i * 2);
        float inv = 1.f / fmaxf((float)__ldg(deg + node), 1.f);
        uint32_t hh, ll;
        pack2h(s.x * inv, s.y * inv, hh, ll);
        ((uint32_t*)agghi)[i] = hh;
        ((uint32_t*)agglo)[i] = ll;
        *(float2*)(aggsum + (size_t)i * 2) = make_float2(0.f, 0.f);
    }
}

// ---------------- launch ------------------------------------------------------
extern "C" void kernel_launch(void* const* d_in, const int* in_sizes, int n_in,
                              void* d_out, int out_size)
{
    const float* x   = (const float*)d_in[0];
    const int*   ei  = (const int*)  d_in[1];
    const float* ea  = (const float*)d_in[2];
    const float* e0w = (const float*)d_in[3];
    const float* e0b = (const float*)d_in[4];
    const float* n0w = (const float*)d_in[5];
    const float* n0b = (const float*)d_in[6];
    const float* ew  = (const float*)d_in[7];
    const float* ebb = (const float*)d_in[8];
    const float* nw  = (const float*)d_in[9];
    const float* nb  = (const float*)d_in[10];
    const float* h1w = (const float*)d_in[11];
    const float* h1b = (const float*)d_in[12];
    const float* h2w = (const float*)d_in[13];
    const float* h2b = (const float*)d_in[14];
    float* out = (float*)d_out;

    h16 *xhi, *xlo, *hAhi, *hAlo, *hBhi, *hBlo, *agghi, *agglo, *eahi, *ealo, *psrc;
    float *pdst, *aggsum;
    uint32_t *w;
    int *deg, *rowptr, *cursor, *srcperm, *nodeof;
    cudaGetSymbolAddress((void**)&xhi,  g_xhi);   cudaGetSymbolAddress((void**)&xlo,  g_xlo);
    cudaGetSymbolAddress((void**)&hAhi, g_hAhi);  cudaGetSymbolAddress((void**)&hAlo, g_hAlo);
    cudaGetSymbolAddress((void**)&hBhi, g_hBhi);  cudaGetSymbolAddress((void**)&hBlo, g_hBlo);
    cudaGetSymbolAddress((void**)&agghi, g_agghi); cudaGetSymbolAddress((void**)&agglo, g_agglo);
    cudaGetSymbolAddress((void**)&psrc, g_psrc);  cudaGetSymbolAddress((void**)&pdst, g_pdst);
    cudaGetSymbolAddress((void**)&aggsum, g_aggsum);
    cudaGetSymbolAddress((void**)&eahi, g_eahi);  cudaGetSymbolAddress((void**)&ealo, g_ealo);
    cudaGetSymbolAddress((void**)&w, g_w);
    cudaGetSymbolAddress((void**)&deg, g_deg);    cudaGetSymbolAddress((void**)&rowptr, g_rowptr);
    cudaGetSymbolAddress((void**)&cursor, g_cursor);
    cudaGetSymbolAddress((void**)&srcperm, g_srcperm);
    cudaGetSymbolAddress((void**)&nodeof, g_nodeof);

    cudaFuncSetAttribute(gemm_one, cudaFuncAttributeMaxDynamicSharedMemorySize, SMEM_BYTES);

    const int* src = ei;
    const int* dst = ei + N_EDGES;

    const int NODE_GRID = (N_NODES + 63) / 64;     // 782
    const int EDGE_GRID = N_EDGES / 64;            // 6250
    const int NORM_BLKS = 1184;

    auto mkjob = [&](const h16* a1h, const h16* a1l, int k1,
                     const uint32_t* b1a, const uint32_t* b1b,
                     const h16* a2h, const h16* a2l, int k2, const uint32_t* b2,
                     const float* bias, const float* w2, int relu, int mode,
                     void* c0, void* c1, int M, int gx) {
        GJob j;
        j.A1hi = a1h; j.A1lo = a1l; j.K1 = k1;
        j.B1a = b1a; j.B1b = b1b;
        j.A2hi = a2h; j.A2lo = a2l; j.K2 = k2; j.B2 = b2;
        j.bias = bias; j.w2 = w2; j.relu = relu; j.mode = mode;
        j.sperm = srcperm; j.nodeof = nodeof; j.psrcp = psrc; j.pdstp = pdst;
        j.C0 = c0; j.C1 = c1; j.M = M; j.gx = gx;
        return j;
    };

    // 1: fused prep
    prep_all<<<WPREP_BLKS + APREP_BLKS + ZERO_BLKS + AGGZ_BLKS, 256>>>(
        e0w, n0w, ew, ew + (size_t)544 * 256, nw, nw + (size_t)512 * 256, h1w, w,
        x, xhi, xlo, deg, out, h2b, aggsum);
    // 2-3: CSR degree + scan
    count_deg_kernel<<<1024, 256>>>(dst, deg, N_EDGES);
    scan_kernel<<<1, 1024>>>(deg, rowptr, cursor, N_NODES);
    // 4: proj0 (profiled by ncu)
    gemm_one<<<NODE_GRID * 4, 256, SMEM_BYTES>>>(
        mkjob(xhi, xlo, IN_C, w + PO0, w + PO1, nullptr, nullptr, 0, nullptr,
              nullptr, nullptr, 0, 3, psrc, pdst, N_NODES, NODE_GRID));
    // 5: scatter + edge-attr convert
    scatter_fused<<<1024, 256>>>(src, dst, ea, cursor, srcperm, nodeof, eahi, ealo, N_EDGES);

    auto mkedge = [&](int woff, const float* ebi) {
        return mkjob(eahi, ealo, 32, w + woff, nullptr,
                     nullptr, nullptr, 0, nullptr,
                     ebi, nullptr, 0, 5, aggsum, nullptr, N_EDGES, EDGE_GRID);
    };

    // ================= layer 0 =================
    gemm_one<<<EDGE_GRID * 2, 256, SMEM_BYTES>>>(mkedge(PO2, e0b));
    normalize_kernel<<<NORM_BLKS, 256>>>(aggsum, deg, agghi, agglo);
    gemm_one<<<NODE_GRID * 2, 256, SMEM_BYTES>>>(
        mkjob(xhi, xlo, IN_C, w + PO3, nullptr, agghi, agglo, HID, w + PO4,
              n0b, nullptr, 1, 2, hAhi, hAlo, N_NODES, NODE_GRID));

    // ================= layers 1..2 =================
    const int peA[2] = {PO5, PO8},  peB[2] = {PO6, PO9},  peE[2] = {PO7, PO10};
    const int pnA[2] = {PO11, PO13}, pnB[2] = {PO12, PO14};
    h16 *curhi = hAhi, *curlo = hAlo, *nxthi = hBhi, *nxtlo = hBlo;
    for (int i = 0; i < 2; ++i) {
        const float* ebi = ebb + (size_t)i * 256;
        const float* nbi = nb + (size_t)i * 256;

        gemm_one<<<NODE_GRID * 4, 256, SMEM_BYTES>>>(
            mkjob(curhi, curlo, HID, w + peA[i], w + peB[i], nullptr, nullptr, 0, nullptr,
                  nullptr, nullptr, 0, 3, psrc, pdst, N_NODES, NODE_GRID));
        gemm_one<<<EDGE_GRID * 2, 256, SMEM_BYTES>>>(mkedge(peE[i], ebi));
        normalize_kernel<<<NORM_BLKS, 256>>>(aggsum, deg, agghi, agglo);
        gemm_one<<<NODE_GRID * 2, 256, SMEM_BYTES>>>(
            mkjob(curhi, curlo, HID, w + pnA[i], nullptr, agghi, agglo, HID, w + pnB[i],
                  nbi, nullptr, 1, 2, nxthi, nxtlo, N_NODES, NODE_GRID));
        h16* t;
        t = curhi; curhi = nxthi; nxthi = t;
        t = curlo; curlo = nxtlo; nxtlo = t;
    }

    // ================= fused head ==========
    gemm_one<<<NODE_GRID * 2, 256, SMEM_BYTES>>>(
        mkjob(curhi, curlo, HID, w + PO15, nullptr, nullptr, nullptr, 0, nullptr,
              h1b, h2w, 1, 4, out, nullptr, N_NODES, NODE_GRID));
}

// round 15
// speedup vs baseline: 1.9690x; 1.9690x over previous
#include <cuda_runtime.h>
#include <cuda_fp16.h>
#include <cstdint>

#define N_NODES 50000
#define N_EDGES 400000
#define IN_C 128
#define HID 256
#define MREP 10

typedef __half h16;

// ---------------- scratch (device globals) ---------------------------------
__device__ __align__(16) h16  g_xhi[(size_t)N_NODES * 128];
__device__ __align__(16) h16  g_xlo[(size_t)N_NODES * 128];
__device__ __align__(16) h16  g_hAhi[(size_t)N_NODES * 256];
__device__ __align__(16) h16  g_hAlo[(size_t)N_NODES * 256];
__device__ __align__(16) h16  g_hBhi[(size_t)N_NODES * 256];
__device__ __align__(16) h16  g_hBlo[(size_t)N_NODES * 256];
__device__ __align__(16) h16  g_agghi[(size_t)N_NODES * 256];
__device__ __align__(16) h16  g_agglo[(size_t)N_NODES * 256];
__device__ __align__(16) h16   g_psrc[(size_t)N_NODES * 256];   // src-proj fp16 (L2-resident)
__device__ __align__(16) float g_pdst[(size_t)N_NODES * 256];   // dst-proj fp32
__device__ __align__(16) h16   g_eproj[(size_t)N_EDGES * 256];  // CSR order
__device__ __align__(16) uint32_t g_ea[(size_t)N_EDGES * 32];   // per-edge 128B: [16 u32 hi][16 u32 lo]
__device__ __align__(16) uint32_t g_w[389120];
__device__ int g_srcperm[N_EDGES];
__device__ int g_deg[N_NODES], g_rowptr[N_NODES + 1], g_cursor[N_NODES];

// piece tables (weight slicing)
__constant__ int c_psel[16]  = {0,0,0,1,1,2,2,2,3,3,3,4,4,5,5,6};
__constant__ int c_prow0[16] = {0,128,256,0,128,0,256,512,0,256,512,0,256,0,256,0};
__constant__ int c_pkw[16]   = {64,64,16,64,128,128,128,16,128,128,16,128,128,128,128,128};
__constant__ int c_poff[17]  = {0,16384,32768,36864,53248,86016,118784,151552,155648,
                                188416,221184,225280,258048,290816,323584,356352,389120};
#define PO0 0
#define PO1 16384
#define PO2 32768
#define PO3 36864
#define PO4 53248
#define PO5 86016
#define PO6 118784
#define PO7 151552
#define PO8 155648
#define PO9 188416
#define PO10 221184
#define PO11 225280
#define PO12 258048
#define PO13 290816
#define PO14 323584
#define PO15 356352

// ---------------- helpers ---------------------------------------------------
__device__ __forceinline__ void pack2h(float a, float b, uint32_t& hi, uint32_t& lo) {
    __half2 h = __floats2half2_rn(a, b);
    __half2 l = __floats2half2_rn(a - __low2float(h), b - __high2float(h));
    hi = *reinterpret_cast<uint32_t*>(&h);
    lo = *reinterpret_cast<uint32_t*>(&l);
}
__device__ __forceinline__ void mma_f16(float* c, const uint32_t* a, const uint32_t* b) {
    asm volatile(
        "mma.sync.aligned.m16n8k16.row.col.f32.f16.f16.f32 "
        "{%0,%1,%2,%3}, {%4,%5,%6,%7}, {%8,%9}, {%0,%1,%2,%3};"
        : "+f"(c[0]), "+f"(c[1]), "+f"(c[2]), "+f"(c[3])
        : "r"(a[0]), "r"(a[1]), "r"(a[2]), "r"(a[3]), "r"(b[0]), "r"(b[1]));
}
__device__ __forceinline__ void ldsm4(uint32_t addr, uint32_t* r) {
    asm volatile("ldmatrix.sync.aligned.m8n8.x4.shared.b16 {%0,%1,%2,%3}, [%4];"
                 : "=r"(r[0]), "=r"(r[1]), "=r"(r[2]), "=r"(r[3]) : "r"(addr));
}
__device__ __forceinline__ void cp_async16(uint32_t daddr, const void* gptr, int src_size) {
    asm volatile("cp.async.cg.shared.global [%0], [%1], 16, %2;"
                 :: "r"(daddr), "l"(gptr), "r"(src_size));
}
#define CP_COMMIT() asm volatile("cp.async.commit_group;" ::: "memory")
#define CP_WAIT1()  asm volatile("cp.async.wait_group 1;" ::: "memory")
#define CP_WAIT0()  asm volatile("cp.async.wait_group 0;" ::: "memory")

// ---------------- fused prep: weights + x split + deg zero + out init -------
#define WPREP_BLKS 1520
#define APREP_BLKS 1024
#define ZERO_BLKS  64
__global__ void prep_all(const float* __restrict__ p0, const float* __restrict__ p1,
                         const float* __restrict__ p2, const float* __restrict__ p3,
                         const float* __restrict__ p4, const float* __restrict__ p5,
                         const float* __restrict__ p6, uint32_t* __restrict__ w,
                         const float* __restrict__ X, h16* __restrict__ xhi, h16* __restrict__ xlo,
                         int* __restrict__ deg, float* __restrict__ outv,
                         const float* __restrict__ h2b) {
    int b = blockIdx.x;
    if (b < WPREP_BLKS) {
        const float* P[7] = {p0, p1, p2, p3, p4, p5, p6};
        const int total = 389120;
        for (int idx = b * blockDim.x + threadIdx.x; idx < total; idx += WPREP_BLKS * blockDim.x) {
            int pc = 0;
            while (idx >= c_poff[pc + 1]) pc++;
            int local = idx - c_poff[pc];
            int Kw = c_pkw[pc];
            int n = local / Kw;
            int kp = local - n * Kw;
            const float* W = P[c_psel[pc]];
            int r = c_prow0[pc] + 2 * kp;
            __half2 h = __floats2half2_rn(W[(size_t)r * 256 + n], W[(size_t)(r + 1) * 256 + n]);
            w[idx] = *reinterpret_cast<uint32_t*>(&h);
        }
    } else if (b < WPREP_BLKS + APREP_BLKS) {
        int bb = b - WPREP_BLKS;
        size_t total = (size_t)N_NODES * 128;
        for (size_t i = (size_t)bb * blockDim.x + threadIdx.x; i < total; i += (size_t)APREP_BLKS * blockDim.x) {
            float v = X[i];
            h16 h = __float2half_rn(v);
            xhi[i] = h;
            xlo[i] = __float2half_rn(v - __half2float(h));
        }
    } else {
        int bb = b - WPREP_BLKS - APREP_BLKS;
        float ob = h2b[0];
        for (int i = bb * blockDim.x + threadIdx.x; i < N_NODES; i += ZERO_BLKS * blockDim.x) {
            deg[i] = 0;
            outv[i] = ob;
        }
    }
}

// ---------------- CSR build ------------------------------------------------
__global__ void count_deg_kernel(const int* __restrict__ dst, int* deg, int e) {
    for (int i = blockIdx.x * blockDim.x + threadIdx.x; i < e; i += gridDim.x * blockDim.x)
        atomicAdd(&deg[dst[i]], 1);
}
__global__ void scan_kernel(const int* __restrict__ deg, int* rowptr, int* cursor, int n) {
    __shared__ int wsum[32];
    __shared__ int carry;
    int tid = threadIdx.x, lane = tid & 31, wid = tid >> 5;
    if (tid == 0) { carry = 0; rowptr[0] = 0; }
    __syncthreads();
    for (int base = 0; base < n; base += 1024) {
        int i = base + tid;
        int v = (i < n) ? deg[i] : 0;
        int cr = carry;
        int x = v;
        #pragma unroll
        for (int off = 1; off < 32; off <<= 1) {
            int t = __shfl_up_sync(0xFFFFFFFFu, x, off);
            if (lane >= off) x += t;
        }
        if (lane == 31) wsum[wid] = x;
        __syncthreads();
        if (wid == 0) {
            int s = wsum[lane];
            #pragma unroll
            for (int off = 1; off < 32; off <<= 1) {
                int t = __shfl_up_sync(0xFFFFFFFFu, s, off);
                if (lane >= off) s += t;
            }
            wsum[lane] = s;
        }
        __syncthreads();
        int warp_off = (wid > 0) ? wsum[wid - 1] : 0;
        int inc = x + warp_off + cr;
        if (i < n) { rowptr[i + 1] = inc; cursor[i] = inc - v; }
        __syncthreads();
        if (tid == 1023) carry = inc;
        __syncthreads();
    }
}
// scatter + edge-attr convert: ONE contiguous 128B row per edge
__global__ void scatter_fused(const int* __restrict__ src, const int* __restrict__ dst,
                              const float* __restrict__ ea,
                              int* cursor, int* __restrict__ src_perm,
                              uint32_t* __restrict__ ea_comb, int e) {
    for (int i = blockIdx.x * blockDim.x + threadIdx.x; i < e; i += gridDim.x * blockDim.x) {
        int p = atomicAdd(&cursor[dst[i]], 1);
        src_perm[p] = src[i];
        const float* row = ea + (size_t)i * 32;
        uint32_t* outp = ea_comb + (size_t)p * 32;
        #pragma unroll
        for (int q = 0; q < 4; ++q) {
            float4 v0 = *(const float4*)(row + q * 8);
            float4 v1 = *(const float4*)(row + q * 8 + 4);
            uint32_t h0, l0, h1, l1, h2, l2, h3, l3;
            pack2h(v0.x, v0.y, h0, l0);
            pack2h(v0.z, v0.w, h1, l1);
            pack2h(v1.x, v1.y, h2, l2);
            pack2h(v1.z, v1.w, h3, l3);
            *(uint4*)(outp + q * 4)      = make_uint4(h0, h1, h2, h3);
            *(uint4*)(outp + 16 + q * 4) = make_uint4(l0, l1, l2, l3);
        }
    }
}

// ---------------- 2-term fp16 GEMM body (job-parameterized) ------------------
#define A_STG 2304    // 64*36 u32 per stage
#define B_STG 2560    // 128*20 u32 per stage
#define SMEM_BYTES (3 * (A_STG + B_STG) * 4)   // 58368

struct GJob {
    const h16 *A1hi, *A1lo;
    const uint32_t *B1a, *B1b;
    const h16 *A2hi, *A2lo;
    const uint32_t *B2;
    const float* bias;
    const float* w2;      // mode 4: head output weights [256]
    void *C0, *C1;
    int K1, K2, relu, mode, M, gx, mrep;
};

__device__ __forceinline__ void gemm_body(const GJob& j, int bxl) {
    extern __shared__ uint32_t dyn[];
    uint32_t sA_saddr = (uint32_t)__cvta_generic_to_shared(dyn);
    uint32_t sB_saddr = (uint32_t)__cvta_generic_to_shared(dyn + 3 * A_STG);

    int tid = threadIdx.x, wid = tid >> 5, lane = tid & 31;
    int xb = bxl % j.gx;
    int yy = bxl / j.gx;
    int bm = xb * 64;
    int bn = (yy & 1) * 128;
    int ysel = yy >> 1;
    int wm = (wid >> 2) * 32;
    int wn = (wid & 3) * 32;
    int gq = lane >> 2, tq = lane & 3;

    int K1 = j.K1, K2 = j.K2;
    int M = j.M;
    int mode = j.mode;

    float acc[2][4][4];
    #pragma unroll
    for (int mi = 0; mi < 2; mi++)
        #pragma unroll
        for (int ni = 0; ni < 4; ni++)
            #pragma unroll
            for (int q = 0; q < 4; q++) acc[mi][ni][q] = 0.f;

    int aLaneRow = ((lane >> 3) & 1) * 8 + (lane & 7);
    int aColSel  = (lane >> 4) * 4;
    uint32_t aOff = (uint32_t)(((wm + aLaneRow) * 36 + aColSel) * 4);
    int bNi      = lane >> 4;
    int bColSel  = ((lane >> 3) & 1) * 4;
    int bLaneRow = lane & 7;
    uint32_t bOff = (uint32_t)(((wn + bNi * 8 + bLaneRow) * 20 + bColSel) * 4);

    // ============== multi-tile edge path: K=32, B loaded once ==============
    if (j.mrep > 1) {
        int mrep = j.mrep;
        const int Kw = 16;     // K=32 -> 16 u32 k-pairs per segment
        const int lda = 32;    // combined 128B rows: hi at +0, lo at +16
        const uint32_t* Ah0 = (const uint32_t*)j.A1hi;
        const uint32_t* Al0 = (const uint32_t*)j.A1lo;
        const uint32_t* Bpp = j.B1a;

        auto issueA = [&](int t, int buf) {
            uint32_t sa = sA_saddr + buf * (A_STG * 4);
            int bmt = (xb * mrep + t) * 64;
            #pragma unroll
            for (int it = 0; it < 2; ++it) {
                int s = tid + it * 256;
                int row = s >> 3, part = s & 7;
                uint32_t so = (uint32_t)((row * 36 + ((part < 4) ? (part * 4) : (16 + (part - 4) * 4))) * 4);
                const uint32_t* gpa = ((part < 4) ? Ah0 : Al0) + (size_t)(bmt + row) * lda + (part & 3) * 4;
                cp_async16(sa + so, gpa, 16);
            }
            CP_COMMIT();
        };
        // group 0: B (+A0)
        #pragma unroll
        for (int it = 0; it < 2; ++it) {
            int s = tid + it * 256;
            int row = s >> 2, part = s & 3;
            uint32_t so = (uint32_t)((row * 20 + part * 4) * 4);
            const uint32_t* gpb = Bpp + (size_t)(bn + row) * Kw + part * 4;
            cp_async16(sB_saddr + so, gpb, 16);
        }
        issueA(0, 0);      // commits group 0 (B + A0)
        issueA(1, 1);      // group 1

        uint32_t bufB = sB_saddr + bOff;
        h16* C = (h16*)j.C0;
        #pragma unroll 1
        for (int t = 0; t < mrep; ++t) {
            int buf = t - (t / 3) * 3;
            if (t + 1 < mrep) { CP_WAIT1(); } else { CP_WAIT0(); }
            __syncthreads();

            #pragma unroll
            for (int mi = 0; mi < 2; mi++)
                #pragma unroll
                for (int ni = 0; ni < 4; ni++)
                    #pragma unroll
                    for (int q = 0; q < 4; q++) acc[mi][ni][q] = 0.f;

            uint32_t bufA = sA_saddr + buf * (A_STG * 4) + aOff;
            #pragma unroll
            for (int ks = 0; ks < 2; ++ks) {
                int kb4 = ks * 32;
                uint32_t bh[4][2], t4[4];
                #pragma unroll
                for (int p = 0; p < 2; ++p) {
                    ldsm4(bufB + p * 1280 + kb4, t4);
                    bh[2 * p][0] = t4[0]; bh[2 * p][1] = t4[1];
                    bh[2 * p + 1][0] = t4[2]; bh[2 * p + 1][1] = t4[3];
                }
                #pragma unroll
                for (int mi = 0; mi < 2; mi++) {
                    uint32_t ah[4], al[4];
                    ldsm4(bufA + mi * 2304 + kb4, ah);
                    ldsm4(bufA + mi * 2304 + kb4 + 64, al);
                    #pragma unroll
                    for (int ni = 0; ni < 4; ni++) mma_f16(acc[mi][ni], ah, bh[ni]);
                    #pragma unroll
                    for (int ni = 0; ni < 4; ni++) mma_f16(acc[mi][ni], al, bh[ni]);
                }
            }
            if (t + 2 < mrep) issueA(t + 2, (t + 2) - ((t + 2) / 3) * 3);

            // epilogue (mode 1): bias + fp16 store, overlaps next tile's loads
            int bmt = (xb * mrep + t) * 64;
            #pragma unroll
            for (int mi = 0; mi < 2; mi++) {
                int r = bmt + wm + mi * 16 + gq;
                #pragma unroll
                for (int ni = 0; ni < 4; ni++) {
                    int gcol = bn + wn + ni * 8 + tq * 2;
                    float b0 = __ldg(j.bias + gcol), b1 = __ldg(j.bias + gcol + 1);
                    float v0 = acc[mi][ni][0] + b0, v1 = acc[mi][ni][1] + b1;
                    float v2 = acc[mi][ni][2] + b0, v3 = acc[mi][ni][3] + b1;
                    if (r < M)     *(__half2*)(C + (size_t)r * 256 + gcol)       = __floats2half2_rn(v0, v1);
                    if (r + 8 < M) *(__half2*)(C + (size_t)(r + 8) * 256 + gcol) = __floats2half2_rn(v2, v3);
                }
            }
        }
        return;
    }

    // ============== generic path ==============
    const uint32_t* Ah[2] = { (const uint32_t*)j.A1hi, (const uint32_t*)j.A2hi };
    const uint32_t* Al[2] = { (const uint32_t*)j.A1lo, (const uint32_t*)j.A2lo };
    const uint32_t* Bp[2] = { ysel ? j.B1b : j.B1a, j.B2 };
    int Kw0 = K1 >> 1, Kw1 = K2 >> 1;
    int nch0 = K1 >> 5;
    int nch = nch0 + ((j.A2hi != nullptr) ? (K2 >> 5) : 0);

    auto issue = [&](int c, int buf) {
        int seg = (c >= nch0) ? 1 : 0;
        int kw0 = (seg ? (c - nch0) : c) << 4;
        int Kw = seg ? Kw1 : Kw0;
        const uint32_t* Ahp = Ah[seg];
        const uint32_t* Alp = Al[seg];
        const uint32_t* Bpp = Bp[seg];
        uint32_t sa = sA_saddr + buf * (A_STG * 4);
        uint32_t sb = sB_saddr + buf * (B_STG * 4);
        #pragma unroll
        for (int it = 0; it < 2; ++it) {
            int s = tid + it * 256;
            int row = s >> 3, part = s & 7;
            uint32_t so = (uint32_t)((row * 36 + ((part < 4) ? (part * 4) : (16 + (part - 4) * 4))) * 4);
            int grow = bm + row;
            int ok = (grow < M);
            int r = ok ? grow : 0;
            const uint32_t* gpa = ((part < 4) ? Ahp : Alp) + (size_t)r * Kw + kw0 + (part & 3) * 4;
            cp_async16(sa + so, gpa, ok ? 16 : 0);
        }
        #pragma unroll
        for (int it = 0; it < 2; ++it) {
            int s = tid + it * 256;
            int row = s >> 2, part = s & 3;
            uint32_t so = (uint32_t)((row * 20 + part * 4) * 4);
            const uint32_t* gpb = Bpp + (size_t)(bn + row) * Kw + kw0 + part * 4;
            cp_async16(sb + so, gpb, 16);
        }
        CP_COMMIT();
    };

    issue(0, 0);
    if (nch > 1) issue(1, 1);

    #pragma unroll 1
    for (int c = 0; c < nch; ++c) {
        int buf = c - (c / 3) * 3;
        if (c + 1 < nch) { CP_WAIT1(); } else { CP_WAIT0(); }
        __syncthreads();

        uint32_t bufA = sA_saddr + buf * (A_STG * 4) + aOff;
        uint32_t bufB = sB_saddr + buf * (B_STG * 4) + bOff;
        #pragma unroll
        for (int ks = 0; ks < 2; ++ks) {
            int kb4 = ks * 32;
            uint32_t bh[4][2], t[4];
            #pragma unroll
            for (int p = 0; p < 2; ++p) {
                ldsm4(bufB + p * 1280 + kb4, t);
                bh[2 * p][0] = t[0]; bh[2 * p][1] = t[1];
                bh[2 * p + 1][0] = t[2]; bh[2 * p + 1][1] = t[3];
            }
            #pragma unroll
            for (int mi = 0; mi < 2; mi++) {
                uint32_t ah[4], al[4];
                ldsm4(bufA + mi * 2304 + kb4, ah);
                ldsm4(bufA + mi * 2304 + kb4 + 64, al);
                #pragma unroll
                for (int ni = 0; ni < 4; ni++) mma_f16(acc[mi][ni], ah, bh[ni]);
                #pragma unroll
                for (int ni = 0; ni < 4; ni++) mma_f16(acc[mi][ni], al, bh[ni]);
            }
        }
        if (c + 2 < nch) {
            int nb = (c + 2) - ((c + 2) / 3) * 3;
            issue(c + 2, nb);
        }
    }

    // epilogue
    float dot0[2] = {0.f, 0.f}, dot1[2] = {0.f, 0.f};
    #pragma unroll
    for (int mi = 0; mi < 2; mi++) {
        int r = bm + wm + mi * 16 + gq;
        #pragma unroll
        for (int ni = 0; ni < 4; ni++) {
            int gcol = bn + wn + ni * 8 + tq * 2;
            float b0 = 0.f, b1 = 0.f;
            if (j.bias) { b0 = __ldg(j.bias + gcol); b1 = __ldg(j.bias + gcol + 1); }
            float v0 = acc[mi][ni][0] + b0, v1 = acc[mi][ni][1] + b1;
            float v2 = acc[mi][ni][2] + b0, v3 = acc[mi][ni][3] + b1;
            if (j.relu) {
                v0 = fmaxf(v0, 0.f); v1 = fmaxf(v1, 0.f);
                v2 = fmaxf(v2, 0.f); v3 = fmaxf(v3, 0.f);
            }
            if (mode == 4) {   // fused MLP head
                float w0v = __ldg(j.w2 + gcol), w1v = __ldg(j.w2 + gcol + 1);
                dot0[mi] += v0 * w0v + v1 * w1v;
                dot1[mi] += v2 * w0v + v3 * w1v;
                continue;
            }
            size_t o0 = (size_t)r * 256 + gcol;
            size_t o1 = (size_t)(r + 8) * 256 + gcol;
            bool w0 = (r < M), w1 = (r + 8 < M);
            if (mode == 0 || (mode == 3 && ysel == 1)) {
                float* C = (mode == 0) ? (float*)j.C0 : (float*)j.C1;
                if (w0) *(float2*)(C + o0) = make_float2(v0, v1);
                if (w1) *(float2*)(C + o1) = make_float2(v2, v3);
            } else if (mode == 1 || mode == 3) {
                h16* C = (h16*)j.C0;
                if (w0) *(__half2*)(C + o0) = __floats2half2_rn(v0, v1);
                if (w1) *(__half2*)(C + o1) = __floats2half2_rn(v2, v3);
            } else {   // mode 2: fp16 hi/lo
                h16* Ch = (h16*)j.C0;
                h16* Cl = (h16*)j.C1;
                if (w0) {
                    uint32_t hh, ll;
                    pack2h(v0, v1, hh, ll);
                    *(uint32_t*)(Ch + o0) = hh;
                    *(uint32_t*)(Cl + o0) = ll;
                }
                if (w1) {
                    uint32_t hh, ll;
                    pack2h(v2, v3, hh, ll);
                    *(uint32_t*)(Ch + o1) = hh;
                    *(uint32_t*)(Cl + o1) = ll;
                }
            }
        }
    }
    if (mode == 4) {
        float* outv = (float*)j.C0;
        #pragma unroll
        for (int mi = 0; mi < 2; mi++) {
            float d0 = dot0[mi], d1 = dot1[mi];
            d0 += __shfl_xor_sync(0xFFFFFFFFu, d0, 1);
            d0 += __shfl_xor_sync(0xFFFFFFFFu, d0, 2);
            d1 += __shfl_xor_sync(0xFFFFFFFFu, d1, 1);
            d1 += __shfl_xor_sync(0xFFFFFFFFu, d1, 2);
            int r = bm + wm + mi * 16 + gq;
            if (tq == 0) {
                if (r < M) atomicAdd(outv + r, d0);
                if (r + 8 < M) atomicAdd(outv + r + 8, d1);
            }
        }
    }
}

__global__ __launch_bounds__(256, 3) void gemm_one(GJob j) {
    gemm_body(j, blockIdx.x);
}
// Dual-job GEMM: Bresenham interleave of job a among a+b CTAs (exact packing).
__global__ __launch_bounds__(256, 3) void gemm_two(GJob a, GJob b, int actas, int total) {
    int bx = blockIdx.x;
    int p0 = (int)(((long long)bx * actas) / total);
    int p1 = (int)(((long long)(bx + 1) * actas) / total);
    if (p1 > p0) gemm_body(a, p0);
    else gemm_body(b, bx - p0);
}

// ---------------- edge aggregation: 128 threads, half2 loads, fp32 math -----
__device__ __forceinline__ float2 addrelu(uint32_t u, uint32_t e, float2 bd) {
    float2 a = __half22float2(*reinterpret_cast<__half2*>(&u));
    float2 b = __half22float2(*reinterpret_cast<__half2*>(&e));
    float2 r;
    r.x = fmaxf(a.x + b.x + bd.x, 0.f);
    r.y = fmaxf(a.y + b.y + bd.y, 0.f);
    return r;
}
__global__ __launch_bounds__(128) void agg_kernel(
    const h16* __restrict__ psrc, const float* __restrict__ pdst,
    const h16* __restrict__ eproj,
    const int* __restrict__ src_perm, const int* __restrict__ rowptr,
    h16* __restrict__ agghi, h16* __restrict__ agglo, int n)
{
    int tid = threadIdx.x;
    const uint32_t* ps = (const uint32_t*)psrc;
    const uint32_t* ep = (const uint32_t*)eproj;
    for (int node = blockIdx.x; node < n; node += gridDim.x) {
        int beg = rowptr[node], end = rowptr[node + 1];
        float2 bd = *(const float2*)(pdst + (size_t)node * 256 + 2 * tid);
        float ax = 0.f, ay = 0.f;
        int p = beg;
        for (; p + 4 <= end; p += 4) {
            int s0 = src_perm[p],     s1 = src_perm[p + 1];
            int s2 = src_perm[p + 2], s3 = src_perm[p + 3];
            uint32_t u0 = ps[(size_t)s0 * 128 + tid], e0 = ep[(size_t)p * 128 + tid];
            uint32_t u1 = ps[(size_t)s1 * 128 + tid], e1 = ep[(size_t)(p + 1) * 128 + tid];
            uint32_t u2 = ps[(size_t)s2 * 128 + tid], e2 = ep[(size_t)(p + 2) * 128 + tid];
            uint32_t u3 = ps[(size_t)s3 * 128 + tid], e3 = ep[(size_t)(p + 3) * 128 + tid];
            float2 f0 = addrelu(u0, e0, bd);
            float2 f1 = addrelu(u1, e1, bd);
            float2 f2 = addrelu(u2, e2, bd);
            float2 f3 = addrelu(u3, e3, bd);
            ax += (f0.x + f1.x) + (f2.x + f3.x);
            ay += (f0.y + f1.y) + (f2.y + f3.y);
        }
        for (; p < end; ++p) {
            uint32_t u = ps[(size_t)src_perm[p] * 128 + tid], e = ep[(size_t)p * 128 + tid];
            float2 f = addrelu(u, e, bd);
            ax += f.x;
            ay += f.y;
        }
        float inv = 1.f / fmaxf((float)(end - beg), 1.f);
        ax *= inv;
        ay *= inv;
        uint32_t hh, ll;
        pack2h(ax, ay, hh, ll);
        *(uint32_t*)(agghi + (size_t)node * 256 + 2 * tid) = hh;
        *(uint32_t*)(agglo + (size_t)node * 256 + 2 * tid) = ll;
    }
}

// ---------------- launch ------------------------------------------------------
extern "C" void kernel_launch(void* const* d_in, const int* in_sizes, int n_in,
                              void* d_out, int out_size)
{
    const float* x   = (const float*)d_in[0];
    const int*   ei  = (const int*)  d_in[1];
    const float* ea  = (const float*)d_in[2];
    const float* e0w = (const float*)d_in[3];
    const float* e0b = (const float*)d_in[4];
    const float* n0w = (const float*)d_in[5];
    const float* n0b = (const float*)d_in[6];
    const float* ew  = (const float*)d_in[7];
    const float* ebb = (const float*)d_in[8];
    const float* nw  = (const float*)d_in[9];
    const float* nb  = (const float*)d_in[10];
    const float* h1w = (const float*)d_in[11];
    const float* h1b = (const float*)d_in[12];
    const float* h2w = (const float*)d_in[13];
    const float* h2b = (const float*)d_in[14];
    float* out = (float*)d_out;

    h16 *xhi, *xlo, *hAhi, *hAlo, *hBhi, *hBlo, *agghi, *agglo, *psrc, *eproj;
    float *pdst;
    uint32_t *w, *eacomb;
    int *deg, *rowptr, *cursor, *srcperm;
    cudaGetSymbolAddress((void**)&xhi,  g_xhi);   cudaGetSymbolAddress((void**)&xlo,  g_xlo);
    cudaGetSymbolAddress((void**)&hAhi, g_hAhi);  cudaGetSymbolAddress((void**)&hAlo, g_hAlo);
    cudaGetSymbolAddress((void**)&hBhi, g_hBhi);  cudaGetSymbolAddress((void**)&hBlo, g_hBlo);
    cudaGetSymbolAddress((void**)&agghi, g_agghi); cudaGetSymbolAddress((void**)&agglo, g_agglo);
    cudaGetSymbolAddress((void**)&psrc, g_psrc);  cudaGetSymbolAddress((void**)&pdst, g_pdst);
    cudaGetSymbolAddress((void**)&eproj, g_eproj);
    cudaGetSymbolAddress((void**)&eacomb, g_ea);
    cudaGetSymbolAddress((void**)&w, g_w);
    cudaGetSymbolAddress((void**)&deg, g_deg);    cudaGetSymbolAddress((void**)&rowptr, g_rowptr);
    cudaGetSymbolAddress((void**)&cursor, g_cursor);
    cudaGetSymbolAddress((void**)&srcperm, g_srcperm);

    cudaFuncSetAttribute(gemm_one, cudaFuncAttributeMaxDynamicSharedMemorySize, SMEM_BYTES);
    cudaFuncSetAttribute(gemm_two, cudaFuncAttributeMaxDynamicSharedMemorySize, SMEM_BYTES);

    const int* src = ei;
    const int* dst = ei + N_EDGES;

    const int NODE_GRID = (N_NODES + 63) / 64;     // 782
    const int EDGE_GX   = N_EDGES / 64 / MREP;     // 625
    const int EDGE_CTAS = EDGE_GX * 2;             // 1250
    const int AGG_BLOCKS = 2368;

    auto mkjob = [](const h16* a1h, const h16* a1l, int k1,
                    const uint32_t* b1a, const uint32_t* b1b,
                    const h16* a2h, const h16* a2l, int k2, const uint32_t* b2,
                    const float* bias, const float* w2, int relu, int mode,
                    void* c0, void* c1, int M, int gx, int mrep) {
        GJob j;
        j.A1hi = a1h; j.A1lo = a1l; j.K1 = k1;
        j.B1a = b1a; j.B1b = b1b;
        j.A2hi = a2h; j.A2lo = a2l; j.K2 = k2; j.B2 = b2;
        j.bias = bias; j.w2 = w2; j.relu = relu; j.mode = mode;
        j.C0 = c0; j.C1 = c1; j.M = M; j.gx = gx; j.mrep = mrep;
        return j;
    };

    // 1: fused prep
    prep_all<<<WPREP_BLKS + APREP_BLKS + ZERO_BLKS, 256>>>(
        e0w, n0w, ew, ew + (size_t)544 * 256, nw, nw + (size_t)512 * 256, h1w, w,
        x, xhi, xlo, deg, out, h2b);
    // 2-3: CSR degree + scan
    count_deg_kernel<<<1024, 256>>>(dst, deg, N_EDGES);
    scan_kernel<<<1, 1024>>>(deg, rowptr, cursor, N_NODES);
    // 4: scatter + edge-attr convert (profiled by ncu; combined 128B rows)
    scatter_fused<<<1024, 256>>>(src, dst, ea, cursor, srcperm, eacomb, N_EDGES);

    auto mkedge = [&](int woff, const float* ebi) {
        return mkjob((const h16*)eacomb, (const h16*)(eacomb + 16), 32,
                     w + woff, nullptr,
                     nullptr, nullptr, 0, nullptr,
                     ebi, nullptr, 0, 1, eproj, nullptr, N_EDGES, EDGE_GX, MREP);
    };

    // ================= layer 0 =================
    // 5: proj0 co-scheduled with edge0
    {
        GJob jproj0 = mkjob(xhi, xlo, IN_C, w + PO0, w + PO1,
                            nullptr, nullptr, 0, nullptr,
                            nullptr, nullptr, 0, 3, psrc, pdst, N_NODES, NODE_GRID, 1);
        int actas = NODE_GRID * 4;          // 3128
        gemm_two<<<actas + EDGE_CTAS, 256, SMEM_BYTES>>>(jproj0, mkedge(PO2, e0b), actas, actas + EDGE_CTAS);
    }
    agg_kernel<<<AGG_BLOCKS, 128>>>(psrc, pdst, eproj, srcperm, rowptr, agghi, agglo, N_NODES);
    // node0 co-scheduled with edge1
    {
        GJob jnode0 = mkjob(xhi, xlo, IN_C, w + PO3, nullptr,
                            agghi, agglo, HID, w + PO4,
                            n0b, nullptr, 1, 2, hAhi, hAlo, N_NODES, NODE_GRID, 1);
        int actas = NODE_GRID * 2;          // 1564
        gemm_two<<<actas + EDGE_CTAS, 256, SMEM_BYTES>>>(jnode0, mkedge(PO7, ebb), actas, actas + EDGE_CTAS);
    }

    // ================= layers 1..2 =================
    const int peA[2] = {PO5, PO8},  peB[2] = {PO6, PO9};
    const int pnA[2] = {PO11, PO13}, pnB[2] = {PO12, PO14};
    h16 *curhi = hAhi, *curlo = hAlo, *nxthi = hBhi, *nxtlo = hBlo;
    for (int i = 0; i < 2; ++i) {
        const float* nbi = nb + (size_t)i * 256;

        GJob jproj = mkjob(curhi, curlo, HID, w + peA[i], w + peB[i],
                           nullptr, nullptr, 0, nullptr,
                           nullptr, nullptr, 0, 3, psrc, pdst, N_NODES, NODE_GRID, 1);
        gemm_one<<<NODE_GRID * 4, 256, SMEM_BYTES>>>(jproj);
        agg_kernel<<<AGG_BLOCKS, 128>>>(psrc, pdst, eproj, srcperm, rowptr, agghi, agglo, N_NODES);
        GJob jnode = mkjob(curhi, curlo, HID, w + pnA[i], nullptr,
                           agghi, agglo, HID, w + pnB[i],
                           nbi, nullptr, 1, 2, nxthi, nxtlo, N_NODES, NODE_GRID, 1);
        if (i == 0) {
            int actas = NODE_GRID * 2;
            gemm_two<<<actas + EDGE_CTAS, 256, SMEM_BYTES>>>(jnode, mkedge(PO10, ebb + 256), actas, actas + EDGE_CTAS);
        } else {
            gemm_one<<<NODE_GRID * 2, 256, SMEM_BYTES>>>(jnode);
        }
        h16* t;
        t = curhi; curhi = nxthi; nxthi = t;
        t = curlo; curlo = nxtlo; nxtlo = t;
    }

    // ================= fused head ==========
    GJob jhead = mkjob(curhi, curlo, HID, w + PO15, nullptr,
                       nullptr, nullptr, 0, nullptr,
                       h1b, h2w, 1, 4, out, nullptr, N_NODES, NODE_GRID, 1);
    gemm_one<<<NODE_GRID * 2, 256, SMEM_BYTES>>>(jhead);
}